// round 17
// baseline (speedup 1.0000x reference)
#include <cuda_runtime.h>
#include <cstdint>

#define NN 8192

// Scratch (allocation-free rule: __device__ globals)
__device__ float g_conv[NN];
__device__ float g_h[NN];

// ---- mbarrier / TMA-bulk helpers ----
__device__ __forceinline__ void mbar_init(uint32_t mbar, uint32_t count) {
    asm volatile("mbarrier.init.shared.b64 [%0], %1;" :: "r"(mbar), "r"(count) : "memory");
}
__device__ __forceinline__ void mbar_expect_tx(uint32_t mbar, uint32_t bytes) {
    asm volatile("mbarrier.arrive.expect_tx.shared.b64 _, [%0], %1;"
                 :: "r"(mbar), "r"(bytes) : "memory");
}
__device__ __forceinline__ void mbar_wait(uint32_t mbar, uint32_t parity) {
    asm volatile(
        "{\n\t"
        ".reg .pred P;\n\t"
        "WAIT_%=:\n\t"
        "mbarrier.try_wait.parity.acquire.cta.shared::cta.b64 P, [%0], %1, 0x989680;\n\t"
        "@P bra.uni DONE_%=;\n\t"
        "bra.uni WAIT_%=;\n\t"
        "DONE_%=:\n\t"
        "}"
        :: "r"(mbar), "r"(parity) : "memory");
}
__device__ __forceinline__ void bulk_copy(uint32_t smem_dst, const void* gsrc,
                                          uint32_t bytes, uint32_t mbar) {
    asm volatile(
        "cp.async.bulk.shared::cta.global.mbarrier::complete_tx::bytes [%0], [%1], %2, [%3];"
        :: "r"(smem_dst), "l"(gsrc), "r"(bytes), "r"(mbar) : "memory");
}

// Kernel 1: per-node 16-wide dot + bias + sigmoid (launch-floor bound)
__global__ void __launch_bounds__(64) conv_sigmoid_kernel(
    const float* __restrict__ nf,
    const float* __restrict__ cw,
    const float* __restrict__ cb) {
    int i = blockIdx.x * 64 + threadIdx.x;
    if (i >= NN) return;
    const float4* row = reinterpret_cast<const float4*>(nf + (size_t)i * 16);
    float4 w0 = reinterpret_cast<const float4*>(cw)[0];
    float4 w1 = reinterpret_cast<const float4*>(cw)[1];
    float4 w2 = reinterpret_cast<const float4*>(cw)[2];
    float4 w3 = reinterpret_cast<const float4*>(cw)[3];
    float4 a0 = row[0], a1 = row[1], a2 = row[2], a3 = row[3];
    float s = a0.x*w0.x + a0.y*w0.y + a0.z*w0.z + a0.w*w0.w
            + a1.x*w1.x + a1.y*w1.y + a1.z*w1.z + a1.w*w1.w
            + a2.x*w2.x + a2.y*w2.y + a2.z*w2.z + a2.w*w2.w
            + a3.x*w3.x + a3.y*w3.y + a3.z*w3.z + a3.w*w3.w;
    s += cb[0];
    g_conv[i] = 1.0f / (1.0f + __expf(-s));
}

// Matvec: one row per 256-thread block. W row fetched as two 16KB
// cp.async.bulk copies (copy engine moves full lines; one instruction per
// half instead of 1024 LDGSTS), pipelined over two mbarriers: wait bar0 ->
// compute half 1, wait bar1 -> compute half 2.
template <int APPLY_TANH>
__global__ void __launch_bounds__(256) matvec_kernel(
    const float* __restrict__ W,
    const float* __restrict__ b,
    const float* __restrict__ x,
    float* __restrict__ y) {
    __shared__ alignas(128) float4 buf[NN / 4];  // 32 KB
    __shared__ alignas(8) uint64_t mbar_store[2];
    __shared__ float red[8];

    const int row = blockIdx.x;
    const int tid = threadIdx.x;
    const float* Wrow = W + (size_t)row * NN;
    const float4* __restrict__ x4 = reinterpret_cast<const float4*>(x);

    const uint32_t sbase = (uint32_t)__cvta_generic_to_shared(buf);
    const uint32_t mb0 = (uint32_t)__cvta_generic_to_shared(&mbar_store[0]);
    const uint32_t mb1 = (uint32_t)__cvta_generic_to_shared(&mbar_store[1]);

    if (tid == 0) {
        mbar_init(mb0, 1);
        mbar_init(mb1, 1);
        asm volatile("fence.proxy.async.shared::cta;" ::: "memory");
    }
    __syncthreads();

    if (tid == 0) {
        mbar_expect_tx(mb0, 16384);
        bulk_copy(sbase, Wrow, 16384, mb0);
        mbar_expect_tx(mb1, 16384);
        bulk_copy(sbase + 16384, Wrow + NN / 2, 16384, mb1);
    }

    float s = 0.0f;

    mbar_wait(mb0, 0);
    #pragma unroll
    for (int j = 0; j < 4; ++j) {
        int i = tid + 256 * j;
        float4 a = buf[i];
        float4 v = x4[i];
        s += a.x * v.x + a.y * v.y + a.z * v.z + a.w * v.w;
    }

    mbar_wait(mb1, 0);
    #pragma unroll
    for (int j = 4; j < 8; ++j) {
        int i = tid + 256 * j;
        float4 a = buf[i];
        float4 v = x4[i];
        s += a.x * v.x + a.y * v.y + a.z * v.z + a.w * v.w;
    }

    #pragma unroll
    for (int o = 16; o > 0; o >>= 1) s += __shfl_xor_sync(0xffffffffu, s, o);
    if ((tid & 31) == 0) red[tid >> 5] = s;
    __syncthreads();
    if (tid < 8) {
        s = red[tid];
        #pragma unroll
        for (int o = 4; o > 0; o >>= 1) s += __shfl_xor_sync(0x000000ffu, s, o);
        if (tid == 0) {
            s += b[row];
            y[row] = APPLY_TANH ? tanhf(s) : s;
        }
    }
}

extern "C" void kernel_launch(void* const* d_in, const int* in_sizes, int n_in,
                              void* d_out, int out_size) {
    const float* node_features = (const float*)d_in[0]; // (8192, 16)
    const float* conv_w        = (const float*)d_in[1]; // (16,)
    const float* conv_b        = (const float*)d_in[2]; // scalar
    const float* W1            = (const float*)d_in[3]; // (8192, 8192)
    const float* b1            = (const float*)d_in[4]; // (8192,)
    const float* W2            = (const float*)d_in[5]; // (8192, 8192)
    const float* b2            = (const float*)d_in[6]; // (8192,)
    float* out = (float*)d_out;

    float* conv_feats;
    float* h;
    cudaGetSymbolAddress((void**)&conv_feats, g_conv);
    cudaGetSymbolAddress((void**)&h, g_h);

    conv_sigmoid_kernel<<<NN / 64, 64>>>(node_features, conv_w, conv_b);
    matvec_kernel<1><<<NN, 256>>>(W1, b1, conv_feats, h);
    matvec_kernel<0><<<NN, 256>>>(W2, b2, h, out);
}